// round 2
// baseline (speedup 1.0000x reference)
#include <cuda_runtime.h>
#include <cstdint>

// Problem dims (fixed by reference)
#define BQ 8
#define CQ 32
#define KQ 512
#define IT 4   // i-rows per block in kernel 1

// Scratch for logits: B*K*K floats = 8 MB. Device global (no allocation allowed).
__device__ float g_logit[BQ * KQ * KQ];

// ---------------------------------------------------------------------------
// Threefry-2x32, 20 rounds, exactly as JAX's threefry2x32 with key (0, 42).
// ---------------------------------------------------------------------------
__device__ __forceinline__ uint32_t rotl32(uint32_t x, int r) {
    return (x << r) | (x >> (32 - r));
}

__device__ __forceinline__ void threefry_0_42(uint32_t x0, uint32_t x1,
                                              uint32_t& o0, uint32_t& o1) {
    const uint32_t ks0 = 0u;
    const uint32_t ks1 = 42u;
    const uint32_t ks2 = 0u ^ 42u ^ 0x1BD11BDAu;

    x0 += ks0; x1 += ks1;

    // group 1: rotations {13,15,26,6}
    x0 += x1; x1 = rotl32(x1, 13); x1 ^= x0;
    x0 += x1; x1 = rotl32(x1, 15); x1 ^= x0;
    x0 += x1; x1 = rotl32(x1, 26); x1 ^= x0;
    x0 += x1; x1 = rotl32(x1, 6);  x1 ^= x0;
    x0 += ks1; x1 += ks2 + 1u;

    // group 2: rotations {17,29,16,24}
    x0 += x1; x1 = rotl32(x1, 17); x1 ^= x0;
    x0 += x1; x1 = rotl32(x1, 29); x1 ^= x0;
    x0 += x1; x1 = rotl32(x1, 16); x1 ^= x0;
    x0 += x1; x1 = rotl32(x1, 24); x1 ^= x0;
    x0 += ks2; x1 += ks0 + 2u;

    // group 3: rotations {13,15,26,6}
    x0 += x1; x1 = rotl32(x1, 13); x1 ^= x0;
    x0 += x1; x1 = rotl32(x1, 15); x1 ^= x0;
    x0 += x1; x1 = rotl32(x1, 26); x1 ^= x0;
    x0 += x1; x1 = rotl32(x1, 6);  x1 ^= x0;
    x0 += ks0; x1 += ks1 + 3u;

    // group 4: rotations {17,29,16,24}
    x0 += x1; x1 = rotl32(x1, 17); x1 ^= x0;
    x0 += x1; x1 = rotl32(x1, 29); x1 ^= x0;
    x0 += x1; x1 = rotl32(x1, 16); x1 ^= x0;
    x0 += x1; x1 = rotl32(x1, 24); x1 ^= x0;
    x0 += ks1; x1 += ks2 + 4u;

    // group 5: rotations {13,15,26,6}
    x0 += x1; x1 = rotl32(x1, 13); x1 ^= x0;
    x0 += x1; x1 = rotl32(x1, 15); x1 ^= x0;
    x0 += x1; x1 = rotl32(x1, 26); x1 ^= x0;
    x0 += x1; x1 = rotl32(x1, 6);  x1 ^= x0;
    x0 += ks2; x1 += ks0 + 5u;

    o0 = x0; o1 = x1;
}

// jax.random.uniform bits->float: floats = bitcast((bits>>9)|0x3f800000)-1,
// u = max(1e-10, floats*1.0f + 1e-10).
__device__ __forceinline__ float jax_uniform(uint32_t bits) {
    float f = __uint_as_float((bits >> 9) | 0x3F800000u) - 1.0f;
    float u = __fadd_rn(f, 1e-10f);
    return fmaxf(u, 1e-10f);
}

__device__ __forceinline__ float gumbel_from_bits(uint32_t bits) {
    float u = jax_uniform(bits);
    return -logf(-logf(u));
}

// Partitionable-threefry random bits for 64-bit flat index idx (< 2^32 here):
// counter = (hi32(idx)=0, lo32(idx)), output = o0 ^ o1.
__device__ __forceinline__ uint32_t jax_bits_partitionable(uint32_t idx) {
    uint32_t o0, o1;
    threefry_0_42(0u, idx, o0, o1);
    return o0 ^ o1;
}

// ---------------------------------------------------------------------------
// Kernel 1: dist -> exp_dist -> rowmax -> p -> logit   (per (b, i) rows)
// grid (KQ/IT, BQ), 512 threads (thread = j)
// ---------------------------------------------------------------------------
__global__ void __launch_bounds__(KQ)
k_logit(const float* __restrict__ amp, const float* __restrict__ ph,
        const float* __restrict__ A,
        const float* __restrict__ wa_p, const float* __restrict__ wp_p) {
    const int b  = blockIdx.y;
    const int i0 = blockIdx.x * IT;
    const int j  = threadIdx.x;

    __shared__ float s_ai[IT][CQ];
    __shared__ float s_pi[IT][CQ];
    __shared__ float s_max[IT][16];

    const float wa = wa_p[0];
    const float wp = wp_p[0];

    if (threadIdx.x < IT * CQ) {
        int t = threadIdx.x / CQ;
        int c = threadIdx.x % CQ;
        s_ai[t][c] = amp[(b * CQ + c) * KQ + i0 + t];
        s_pi[t][c] = ph[(b * CQ + c) * KQ + i0 + t];
    }
    __syncthreads();

    const float Ajj = A[j * KQ + j];
    float acc[IT];
#pragma unroll
    for (int t = 0; t < IT; t++) acc[t] = 0.0f;

    const float* ap = amp + (size_t)b * CQ * KQ + j;
    const float* pp = ph  + (size_t)b * CQ * KQ + j;

#pragma unroll 4
    for (int c = 0; c < CQ; c++) {
        float aj = ap[c * KQ];
        float pj = pp[c * KQ];
#pragma unroll
        for (int t = 0; t < IT; t++) {
            // exact op-for-op replication of the reference (no fma contraction)
            float ad = __fsub_rn(s_ai[t][c], aj);
            float pd = __fsub_rn(s_pi[t][c], pj);
            float f  = __fadd_rn(__fmul_rn(wa, ad), __fmul_rn(wp, pd));
            float tt = __fmul_rn(f, Ajj);
            acc[t]   = __fadd_rn(acc[t], __fmul_rn(tt, tt));
        }
    }

    float ed[IT];
#pragma unroll
    for (int t = 0; t < IT; t++) {
        float d = __fadd_rn(acc[t], 1e-10f);
        float e = __fdiv_rn(1.0f, d);
        if (j == i0 + t) e = 0.0f;   // offdiag mask before the max
        ed[t] = e;
        float m = e;
#pragma unroll
        for (int o = 16; o > 0; o >>= 1)
            m = fmaxf(m, __shfl_xor_sync(0xFFFFFFFFu, m, o));
        if ((threadIdx.x & 31) == 0) s_max[t][threadIdx.x >> 5] = m;
    }
    __syncthreads();

#pragma unroll
    for (int t = 0; t < IT; t++) {
        float m = s_max[t][0];
#pragma unroll
        for (int w = 1; w < 16; w++) m = fmaxf(m, s_max[t][w]);

        float p;
        if (j == i0 + t) {
            p = 0.99f;                                   // (0*offdiag + 1) * 0.99
        } else {
            p = __fmul_rn(__fdiv_rn(ed[t], m), 0.99f);   // (exp/max) * 0.99
        }
        float logit = logf(__fdiv_rn(p, __fsub_rn(1.0f, p)));
        g_logit[((size_t)b * KQ + (i0 + t)) * KQ + j] = logit;
    }
}

// ---------------------------------------------------------------------------
// Kernel 2: gumbel sampling + mean over batch. grid KQ (block=i), 512 thr (j).
// Partitionable threefry: bits(idx) = o0 ^ o1 of threefry(key, (0, idx)),
// idx = flat index into (B, K, K, 2).
// Early-out: gumbel in [-3.14, 16.64] -> g1 - g0 in [-19.8, 19.8], so
// |2*logit| >= 20 decides without any hashing.
// ---------------------------------------------------------------------------
__global__ void __launch_bounds__(KQ)
k_sample(float* __restrict__ out) {
    const int i = blockIdx.x;
    const int j = threadIdx.x;

    int cnt = 0;
#pragma unroll
    for (int b = 0; b < BQ; b++) {
        float l = g_logit[((size_t)b * KQ + i) * KQ + j];
        float twol = __fadd_rn(l, l);
        if (twol <= -20.0f) continue;               // certain 0
        if (twol >= 20.0f) { cnt++; continue; }     // certain 1

        uint32_t base = (uint32_t)(((b * KQ + i) * KQ + j) * 2);
        float g0 = gumbel_from_bits(jax_bits_partitionable(base));      // comp 0
        float g1 = gumbel_from_bits(jax_bits_partitionable(base + 1u)); // comp 1

        // argmax over {logit+g0, -logit+g1}; ties -> index 0 -> sample=1
        cnt += (__fadd_rn(l, g0) >= __fadd_rn(-l, g1)) ? 1 : 0;
    }
    out[i * KQ + j] = (float)cnt * 0.125f;
}

// ---------------------------------------------------------------------------
extern "C" void kernel_launch(void* const* d_in, const int* in_sizes, int n_in,
                              void* d_out, int out_size) {
    const float* amp = (const float*)d_in[0];   // (B, C, K)
    const float* ph  = (const float*)d_in[1];   // (B, C, K)
    const float* A   = (const float*)d_in[2];   // (K, K)
    const float* wa  = (const float*)d_in[3];   // scalar
    const float* wp  = (const float*)d_in[4];   // scalar
    float* out = (float*)d_out;                  // (K, K)

    dim3 g1(KQ / IT, BQ);
    k_logit<<<g1, KQ>>>(amp, ph, A, wa, wp);
    k_sample<<<KQ, KQ>>>(out);
}

// round 3
// speedup vs baseline: 1.3614x; 1.3614x over previous
#include <cuda_runtime.h>
#include <cstdint>

#define BQ 8
#define CQ 32
#define KQ 512
#define IT 8            // i-rows per block in kernel 1 (4 f32x2 pairs)
#define NPAIR (IT/2)

// Uncertain-decision list (worst case B*K*K entries)
__device__ uint32_t g_cnt;
__device__ uint32_t g_key[BQ * KQ * KQ];   // (b<<18)|(i<<9)|j
__device__ float    g_lg [BQ * KQ * KQ];   // logit

// ---------------------------------------------------------------------------
// f32x2 packed helpers (two independent rn-rounded fp32 lanes per instr;
// bit-identical to the scalar op sequence)
// ---------------------------------------------------------------------------
__device__ __forceinline__ uint64_t pack2(float lo, float hi) {
    uint64_t r; asm("mov.b64 %0, {%1,%2};" : "=l"(r) : "f"(lo), "f"(hi)); return r;
}
__device__ __forceinline__ uint64_t add2(uint64_t a, uint64_t b) {
    uint64_t r; asm("add.rn.f32x2 %0, %1, %2;" : "=l"(r) : "l"(a), "l"(b)); return r;
}
__device__ __forceinline__ uint64_t mul2(uint64_t a, uint64_t b) {
    uint64_t r; asm("mul.rn.f32x2 %0, %1, %2;" : "=l"(r) : "l"(a), "l"(b)); return r;
}
__device__ __forceinline__ void unpack2(uint64_t v, float& lo, float& hi) {
    asm("mov.b64 {%0,%1}, %2;" : "=f"(lo), "=f"(hi) : "l"(v));
}

// ---------------------------------------------------------------------------
// Threefry-2x32, key (0, 42)
// ---------------------------------------------------------------------------
__device__ __forceinline__ uint32_t rotl32(uint32_t x, int r) {
    return (x << r) | (x >> (32 - r));
}
__device__ __forceinline__ void threefry_0_42(uint32_t x0, uint32_t x1,
                                              uint32_t& o0, uint32_t& o1) {
    const uint32_t ks0 = 0u, ks1 = 42u, ks2 = 0u ^ 42u ^ 0x1BD11BDAu;
    x0 += ks0; x1 += ks1;
    x0 += x1; x1 = rotl32(x1, 13); x1 ^= x0;
    x0 += x1; x1 = rotl32(x1, 15); x1 ^= x0;
    x0 += x1; x1 = rotl32(x1, 26); x1 ^= x0;
    x0 += x1; x1 = rotl32(x1, 6);  x1 ^= x0;
    x0 += ks1; x1 += ks2 + 1u;
    x0 += x1; x1 = rotl32(x1, 17); x1 ^= x0;
    x0 += x1; x1 = rotl32(x1, 29); x1 ^= x0;
    x0 += x1; x1 = rotl32(x1, 16); x1 ^= x0;
    x0 += x1; x1 = rotl32(x1, 24); x1 ^= x0;
    x0 += ks2; x1 += ks0 + 2u;
    x0 += x1; x1 = rotl32(x1, 13); x1 ^= x0;
    x0 += x1; x1 = rotl32(x1, 15); x1 ^= x0;
    x0 += x1; x1 = rotl32(x1, 26); x1 ^= x0;
    x0 += x1; x1 = rotl32(x1, 6);  x1 ^= x0;
    x0 += ks0; x1 += ks1 + 3u;
    x0 += x1; x1 = rotl32(x1, 17); x1 ^= x0;
    x0 += x1; x1 = rotl32(x1, 29); x1 ^= x0;
    x0 += x1; x1 = rotl32(x1, 16); x1 ^= x0;
    x0 += x1; x1 = rotl32(x1, 24); x1 ^= x0;
    x0 += ks1; x1 += ks2 + 4u;
    x0 += x1; x1 = rotl32(x1, 13); x1 ^= x0;
    x0 += x1; x1 = rotl32(x1, 15); x1 ^= x0;
    x0 += x1; x1 = rotl32(x1, 26); x1 ^= x0;
    x0 += x1; x1 = rotl32(x1, 6);  x1 ^= x0;
    x0 += ks2; x1 += ks0 + 5u;
    o0 = x0; o1 = x1;
}

__device__ __forceinline__ uint32_t jax_bits_partitionable(uint32_t idx) {
    uint32_t o0, o1;
    threefry_0_42(0u, idx, o0, o1);
    return o0 ^ o1;
}
__device__ __forceinline__ float gumbel_from_bits(uint32_t bits) {
    float f = __uint_as_float((bits >> 9) | 0x3F800000u) - 1.0f;
    float u = fmaxf(__fadd_rn(f, 1e-10f), 1e-10f);
    return -logf(-logf(u));
}

// ---------------------------------------------------------------------------
// Kernel 1: logits + uncertain-list compaction.
// grid (KQ/IT, BQ), 512 threads (thread = j). f32x2 over i-row pairs.
// ---------------------------------------------------------------------------
__global__ void __launch_bounds__(KQ)
k_logit(const float* __restrict__ amp, const float* __restrict__ ph,
        const float* __restrict__ A,
        const float* __restrict__ wa_p, const float* __restrict__ wp_p) {
    const int b  = blockIdx.y;
    const int i0 = blockIdx.x * IT;
    const int j  = threadIdx.x;

    // smem tiles: [c][t] with t contiguous so a t-pair is one aligned 8B word
    __shared__ uint64_t s_a2[CQ][NPAIR];
    __shared__ uint64_t s_p2[CQ][NPAIR];
    __shared__ float    s_max[IT][16];
    __shared__ uint32_t s_cnt;
    __shared__ uint32_t s_base;

    const float wa = wa_p[0];
    const float wp = wp_p[0];

    if (threadIdx.x == 0) s_cnt = 0;
    if (threadIdx.x < IT * CQ) {
        int t = threadIdx.x % IT;
        int c = threadIdx.x / IT;
        ((float*)&s_a2[c][0])[t] = amp[(b * CQ + c) * KQ + i0 + t];
        ((float*)&s_p2[c][0])[t] = ph [(b * CQ + c) * KQ + i0 + t];
    }
    __syncthreads();

    const float Ajj = A[j * KQ + j];
    const uint64_t wa2 = pack2(wa, wa);
    const uint64_t wp2 = pack2(wp, wp);
    const uint64_t A2  = pack2(Ajj, Ajj);

    uint64_t acc2[NPAIR];
#pragma unroll
    for (int p = 0; p < NPAIR; p++) acc2[p] = 0ull;

    const float* ap = amp + (size_t)b * CQ * KQ + j;
    const float* pp = ph  + (size_t)b * CQ * KQ + j;

#pragma unroll 4
    for (int c = 0; c < CQ; c++) {
        float aj = ap[c * KQ];
        float pj = pp[c * KQ];
        uint64_t naj2 = pack2(-aj, -aj);
        uint64_t npj2 = pack2(-pj, -pj);
#pragma unroll
        for (int p = 0; p < NPAIR; p++) {
            // exact replication: ad = s - aj (as s + (-aj)), f = wa*ad + wp*pd,
            // tt = f*Ajj, acc += tt*tt — each lane rn-rounded like the scalar ref.
            uint64_t ad2 = add2(s_a2[c][p], naj2);
            uint64_t pd2 = add2(s_p2[c][p], npj2);
            uint64_t f2  = add2(mul2(wa2, ad2), mul2(wp2, pd2));
            uint64_t tt2 = mul2(f2, A2);
            acc2[p] = add2(acc2[p], mul2(tt2, tt2));
        }
    }

    float acc[IT], ed[IT];
#pragma unroll
    for (int p = 0; p < NPAIR; p++) unpack2(acc2[p], acc[2 * p], acc[2 * p + 1]);

#pragma unroll
    for (int t = 0; t < IT; t++) {
        float d = __fadd_rn(acc[t], 1e-10f);
        float e = __fdiv_rn(1.0f, d);
        if (j == i0 + t) e = 0.0f;           // offdiag mask before the max
        ed[t] = e;
        float m = e;
#pragma unroll
        for (int o = 16; o > 0; o >>= 1)
            m = fmaxf(m, __shfl_xor_sync(0xFFFFFFFFu, m, o));
        if ((threadIdx.x & 31) == 0) s_max[t][threadIdx.x >> 5] = m;
    }
    __syncthreads();

    float lg[IT];
    int nunc = 0;
    int tlist[IT];
#pragma unroll
    for (int t = 0; t < IT; t++) {
        float m = s_max[t][0];
#pragma unroll
        for (int w = 1; w < 16; w++) m = fmaxf(m, s_max[t][w]);
        float p;
        if (j == i0 + t) p = 0.99f;                               // (0 + 1)*0.99
        else             p = __fmul_rn(__fdiv_rn(ed[t], m), 0.99f);
        float l = logf(__fdiv_rn(p, __fsub_rn(1.0f, p)));
        lg[t] = l;
        // certain-0 iff 2l <= -20 (certain-1 impossible: l <= log(99) ~ 4.6)
        if (!(__fadd_rn(l, l) <= -20.0f)) tlist[nunc++] = t;
    }

    int rank = 0;
    if (nunc > 0) rank = atomicAdd(&s_cnt, (uint32_t)nunc);
    __syncthreads();
    if (threadIdx.x == 0 && s_cnt > 0) s_base = atomicAdd(&g_cnt, s_cnt);
    __syncthreads();

    for (int q = 0; q < nunc; q++) {
        int t = tlist[q];
        uint32_t idx = s_base + rank + q;
        g_key[idx] = ((uint32_t)b << 18) | ((uint32_t)(i0 + t) << 9) | (uint32_t)j;
        g_lg [idx] = lg[t];
    }
}

// ---------------------------------------------------------------------------
// Kernel 2: process the compacted uncertain list, scatter exact 1/8 adds.
// ---------------------------------------------------------------------------
__global__ void __launch_bounds__(256)
k_sample2(float* __restrict__ out) {
    const uint32_t n = g_cnt;
    const uint32_t stride = gridDim.x * blockDim.x;
    for (uint32_t k = blockIdx.x * blockDim.x + threadIdx.x; k < n; k += stride) {
        uint32_t key = g_key[k];
        float l = g_lg[k];
        uint32_t flat = key << 1;      // flat index into (B,K,K,2)
        float g0 = gumbel_from_bits(jax_bits_partitionable(flat));
        float g1 = gumbel_from_bits(jax_bits_partitionable(flat + 1u));
        // argmax over {l+g0, -l+g1}; tie -> index 0 -> sample = 1
        if (__fadd_rn(l, g0) >= __fadd_rn(-l, g1))
            atomicAdd(out + (key & 0x3FFFFu), 0.125f);   // exact multiples of 1/8
    }
}

// ---------------------------------------------------------------------------
extern "C" void kernel_launch(void* const* d_in, const int* in_sizes, int n_in,
                              void* d_out, int out_size) {
    const float* amp = (const float*)d_in[0];   // (B, C, K)
    const float* ph  = (const float*)d_in[1];   // (B, C, K)
    const float* A   = (const float*)d_in[2];   // (K, K)
    const float* wa  = (const float*)d_in[3];   // scalar
    const float* wp  = (const float*)d_in[4];   // scalar
    float* out = (float*)d_out;                  // (K, K)

    void* cnt_addr = nullptr;
    cudaGetSymbolAddress(&cnt_addr, g_cnt);
    cudaMemsetAsync(cnt_addr, 0, sizeof(uint32_t));
    cudaMemsetAsync(out, 0, KQ * KQ * sizeof(float));

    dim3 g1(KQ / IT, BQ);
    k_logit<<<g1, KQ>>>(amp, ph, A, wa, wp);
    k_sample2<<<1024, 256>>>(out);
}